// round 2
// baseline (speedup 1.0000x reference)
#include <cuda_runtime.h>
#include <stdint.h>

// Problem constants
#define BATCH 4096
#define FEAT  4096
#define NP    16
#define DDIM  256
#define MROWS (BATCH * NP)   // 65536
#define EPS   1e-5f
#define INV_SCALE 0.0625f    // 1/sqrt(256)

// ---------------- device scratch ----------------
#define RCHUNKS 32
__device__ float g_psum[RCHUNKS * FEAT];
__device__ float g_psumsq[RCHUNKS * FEAT];
__device__ float g_scale[FEAT];
__device__ float g_shift[FEAT];
__device__ float2 g_xn2[(size_t)MROWS * DDIM];   // normalized x, (tf32-hi, lo) pairs, 128 MB
__device__ float2 g_w2[3 * DDIM * DDIM];         // split weights [w][n][k]
__device__ float g_q[(size_t)MROWS * DDIM];
__device__ float g_k[(size_t)MROWS * DDIM];
__device__ float g_v[(size_t)MROWS * DDIM];

__device__ __forceinline__ uint32_t f2tf32(float x) {
    uint32_t r;
    asm("cvt.rna.tf32.f32 %0, %1;" : "=r"(r) : "f"(x));
    return r;
}
__device__ __forceinline__ float2 tf32split(float x) {
    uint32_t hi = f2tf32(x);
    float hif = __uint_as_float(hi);
    float lo = x - hif;
    return make_float2(hif, __uint_as_float(f2tf32(lo)));
}

// ---------------- BN pass 1 ----------------
__global__ void bn_pass1(const float* __restrict__ x) {
    int col = blockIdx.x * 256 + threadIdx.x;
    int r0  = blockIdx.y * (BATCH / RCHUNKS);
    float s = 0.f, ss = 0.f;
    #pragma unroll 4
    for (int r = 0; r < BATCH / RCHUNKS; r++) {
        float v = x[(size_t)(r0 + r) * FEAT + col];
        s += v; ss += v * v;
    }
    g_psum[blockIdx.y * FEAT + col]   = s;
    g_psumsq[blockIdx.y * FEAT + col] = ss;
}

// ---------------- BN pass 2 ----------------
__global__ void bn_pass2(const float* __restrict__ gamma,
                         const float* __restrict__ beta) {
    int col = blockIdx.x * blockDim.x + threadIdx.x;
    float s = 0.f, ss = 0.f;
    #pragma unroll
    for (int c = 0; c < RCHUNKS; c++) {
        s  += g_psum[c * FEAT + col];
        ss += g_psumsq[c * FEAT + col];
    }
    float mean = s * (1.f / BATCH);
    float var  = ss * (1.f / BATCH) - mean * mean;
    float rstd = rsqrtf(var + EPS);
    float a = rstd * gamma[col];
    g_scale[col] = a;
    g_shift[col] = beta[col] - mean * a;
}

// ---------------- normalize + tf32 split: xn -> (hi,lo) float2 ----------------
__global__ void normalize_split(const float* __restrict__ x) {
    int i = blockIdx.x * blockDim.x + threadIdx.x;   // float4 index over x
    const float4* x4 = (const float4*)x;
    float4* o4 = (float4*)g_xn2;
    int col = (i & (FEAT / 4 - 1)) * 4;
    float4 v = x4[i];
    float2 a = tf32split(v.x * g_scale[col + 0] + g_shift[col + 0]);
    float2 b = tf32split(v.y * g_scale[col + 1] + g_shift[col + 1]);
    float2 c = tf32split(v.z * g_scale[col + 2] + g_shift[col + 2]);
    float2 d = tf32split(v.w * g_scale[col + 3] + g_shift[col + 3]);
    o4[i * 2 + 0] = make_float4(a.x, a.y, b.x, b.y);
    o4[i * 2 + 1] = make_float4(c.x, c.y, d.x, d.y);
}

// ---------------- weight split (one-shot, tiny) ----------------
__global__ void wsplit(const float* __restrict__ wq,
                       const float* __restrict__ wk,
                       const float* __restrict__ wv) {
    int tid = blockIdx.x * blockDim.x + threadIdx.x;   // 0 .. 3*65536-1
    int w = tid >> 16;
    const float* src = (w == 0) ? wq : (w == 1) ? wk : wv;
    g_w2[tid] = tf32split(src[tid & 65535]);
}

// ---------------- tensor-core QKV GEMM (3xTF32 split) ----------------
// C[m,n] = sum_k xn[m,k] * W[n,k] + bias[n].  M=65536, N=256, K=256.
// BM=128 (8 warps x m16), BN=64, BK=16. grid (4, 512, 3).
#define AP 18   // smem pitch in float2 for A rows (BK=16 + 2 pad)
#define BP 18
__global__ void __launch_bounds__(256, 2) gemm3_mma(
    const float* __restrict__ bq, const float* __restrict__ bk2,
    const float* __restrict__ bv)
{
    __shared__ float2 sA[128 * AP];   // [m][k] hi/lo
    __shared__ float2 sB[64 * BP];    // [n][k] hi/lo

    int m0 = blockIdx.y * 128;
    int n0 = blockIdx.x * 64;
    int w  = blockIdx.z;
    const float2* W2 = g_w2 + (size_t)w * DDIM * DDIM;
    const float* bias = (w == 0) ? bq : (w == 1) ? bk2 : bv;
    float* out = (w == 0) ? g_q : (w == 1) ? g_k : g_v;

    int tid = threadIdx.x;
    int lane = tid & 31;
    int warp = tid >> 5;            // 0..7
    int warpM = warp * 16;
    int l4 = lane & 3;              // k sub-index
    int g4 = lane >> 2;             // row/col group 0..7

    float acc[8][4];
    #pragma unroll
    for (int nt = 0; nt < 8; nt++)
        #pragma unroll
        for (int i = 0; i < 4; i++) acc[nt][i] = 0.f;

    // load mappings
    int arow = tid >> 1;                 // 0..127
    int akp  = (tid & 1) * 8;            // 0 or 8 (float2 units)
    int brow = tid >> 2;                 // 0..63
    int bkp  = (tid & 3) * 4;            // 0,4,8,12

    for (int k0 = 0; k0 < DDIM; k0 += 16) {
        // A tile: 128 x 16 float2
        {
            const float4* src = (const float4*)&g_xn2[(size_t)(m0 + arow) * DDIM + k0 + akp];
            float4* dst = (float4*)&sA[arow * AP + akp];
            #pragma unroll
            for (int j = 0; j < 4; j++) dst[j] = src[j];
        }
        // B tile: 64 x 16 float2
        {
            const float4* src = (const float4*)&W2[(size_t)(n0 + brow) * DDIM + k0 + bkp];
            float4* dst = (float4*)&sB[brow * BP + bkp];
            dst[0] = src[0];
            dst[1] = src[1];
        }
        __syncthreads();

        #pragma unroll
        for (int kk = 0; kk < 16; kk += 8) {
            // A fragment (m16k8): rows warpM+g4, warpM+g4+8; cols kk+l4, kk+l4+4
            float2 a0 = sA[(warpM + g4) * AP + kk + l4];
            float2 a1 = sA[(warpM + g4 + 8) * AP + kk + l4];
            float2 a2 = sA[(warpM + g4) * AP + kk + l4 + 4];
            float2 a3 = sA[(warpM + g4 + 8) * AP + kk + l4 + 4];
            uint32_t ah0 = __float_as_uint(a0.x), al0 = __float_as_uint(a0.y);
            uint32_t ah1 = __float_as_uint(a1.x), al1 = __float_as_uint(a1.y);
            uint32_t ah2 = __float_as_uint(a2.x), al2 = __float_as_uint(a2.y);
            uint32_t ah3 = __float_as_uint(a3.x), al3 = __float_as_uint(a3.y);

            #pragma unroll
            for (int nt = 0; nt < 8; nt++) {
                // B fragment (k8n8): b0 = B[kk+l4][nt*8+g4], b1 = B[kk+l4+4][...]
                float2 b0 = sB[(nt * 8 + g4) * BP + kk + l4];
                float2 b1 = sB[(nt * 8 + g4) * BP + kk + l4 + 4];
                uint32_t bh0 = __float_as_uint(b0.x), bl0 = __float_as_uint(b0.y);
                uint32_t bh1 = __float_as_uint(b1.x), bl1 = __float_as_uint(b1.y);
                float* c = acc[nt];
                // hi*hi
                asm volatile(
                    "mma.sync.aligned.m16n8k8.row.col.f32.tf32.tf32.f32 "
                    "{%0,%1,%2,%3}, {%4,%5,%6,%7}, {%8,%9}, {%0,%1,%2,%3};"
                    : "+f"(c[0]), "+f"(c[1]), "+f"(c[2]), "+f"(c[3])
                    : "r"(ah0), "r"(ah1), "r"(ah2), "r"(ah3), "r"(bh0), "r"(bh1));
                // hi*lo
                asm volatile(
                    "mma.sync.aligned.m16n8k8.row.col.f32.tf32.tf32.f32 "
                    "{%0,%1,%2,%3}, {%4,%5,%6,%7}, {%8,%9}, {%0,%1,%2,%3};"
                    : "+f"(c[0]), "+f"(c[1]), "+f"(c[2]), "+f"(c[3])
                    : "r"(ah0), "r"(ah1), "r"(ah2), "r"(ah3), "r"(bl0), "r"(bl1));
                // lo*hi
                asm volatile(
                    "mma.sync.aligned.m16n8k8.row.col.f32.tf32.tf32.f32 "
                    "{%0,%1,%2,%3}, {%4,%5,%6,%7}, {%8,%9}, {%0,%1,%2,%3};"
                    : "+f"(c[0]), "+f"(c[1]), "+f"(c[2]), "+f"(c[3])
                    : "r"(al0), "r"(al1), "r"(al2), "r"(al3), "r"(bh0), "r"(bh1));
            }
        }
        __syncthreads();
    }

    // epilogue: C frag c0/c1 at (row=g4, col=2*l4[,+1]), c2/c3 at (row=g4+8)
    #pragma unroll
    for (int nt = 0; nt < 8; nt++) {
        int col = n0 + nt * 8 + l4 * 2;
        float bx = bias[col], by = bias[col + 1];
        int r0 = m0 + warpM + g4;
        *(float2*)&out[(size_t)r0 * DDIM + col] =
            make_float2(acc[nt][0] + bx, acc[nt][1] + by);
        *(float2*)&out[(size_t)(r0 + 8) * DDIM + col] =
            make_float2(acc[nt][2] + bx, acc[nt][3] + by);
    }
}

// ---------------- per-batch attention (unchanged, single-pass softmax) ----
__global__ void __launch_bounds__(128) attn_k(const float* __restrict__ x,
                                              float* __restrict__ out)
{
    __shared__ float Qs[NP * DDIM];
    __shared__ float Ks[NP * DDIM];
    __shared__ float Vs[NP * DDIM];

    int b = blockIdx.x;
    int tid = threadIdx.x;

    {
        const float4* qsrc = (const float4*)(g_q + (size_t)b * (NP * DDIM));
        const float4* ksrc = (const float4*)(g_k + (size_t)b * (NP * DDIM));
        const float4* vsrc = (const float4*)(g_v + (size_t)b * (NP * DDIM));
        float4* qd = (float4*)Qs; float4* kd = (float4*)Ks; float4* vd = (float4*)Vs;
        #pragma unroll
        for (int i = tid; i < NP * DDIM / 4; i += 128) {
            qd[i] = qsrc[i]; kd[i] = ksrc[i]; vd[i] = vsrc[i];
        }
    }
    __syncthreads();

    int e0 = tid;
    float q0[NP], q1[NP];
    #pragma unroll
    for (int p = 0; p < NP; p++) {
        q0[p] = Qs[p * DDIM + e0];
        q1[p] = Qs[p * DDIM + e0 + 128];
    }
    float o0[NP], o1[NP];
    #pragma unroll
    for (int p = 0; p < NP; p++) { o0[p] = 0.f; o1[p] = 0.f; }
    float s0 = 0.f, s1 = 0.f;

    const float4* K4 = (const float4*)Ks;
    const float4* V4 = (const float4*)Vs;

    for (int f4 = 0; f4 < DDIM / 4; f4++) {
        float d00 = 0.f, d01 = 0.f, d02 = 0.f, d03 = 0.f;
        float d10 = 0.f, d11 = 0.f, d12 = 0.f, d13 = 0.f;
        #pragma unroll
        for (int p = 0; p < NP; p++) {
            float4 kk = K4[p * (DDIM / 4) + f4];
            d00 += q0[p] * kk.x; d01 += q0[p] * kk.y;
            d02 += q0[p] * kk.z; d03 += q0[p] * kk.w;
            d10 += q1[p] * kk.x; d11 += q1[p] * kk.y;
            d12 += q1[p] * kk.z; d13 += q1[p] * kk.w;
        }
        float t00 = __expf(d00 * INV_SCALE), t01 = __expf(d01 * INV_SCALE);
        float t02 = __expf(d02 * INV_SCALE), t03 = __expf(d03 * INV_SCALE);
        float t10 = __expf(d10 * INV_SCALE), t11 = __expf(d11 * INV_SCALE);
        float t12 = __expf(d12 * INV_SCALE), t13 = __expf(d13 * INV_SCALE);
        s0 += (t00 + t01) + (t02 + t03);
        s1 += (t10 + t11) + (t12 + t13);
        #pragma unroll
        for (int p = 0; p < NP; p++) {
            float4 vv = V4[p * (DDIM / 4) + f4];
            o0[p] += t00 * vv.x + t01 * vv.y + t02 * vv.z + t03 * vv.w;
            o1[p] += t10 * vv.x + t11 * vv.y + t12 * vv.z + t13 * vv.w;
        }
    }

    float inv0 = 1.f / s0, inv1 = 1.f / s1;
    {
        size_t base = (size_t)b * FEAT + (size_t)e0 * NP;
        #pragma unroll
        for (int p4 = 0; p4 < 4; p4++) {
            float4 xr = *(const float4*)&x[base + p4 * 4];
            float4 r;
            r.x = o0[p4 * 4 + 0] * inv0 + xr.x;
            r.y = o0[p4 * 4 + 1] * inv0 + xr.y;
            r.z = o0[p4 * 4 + 2] * inv0 + xr.z;
            r.w = o0[p4 * 4 + 3] * inv0 + xr.w;
            *(float4*)&out[base + p4 * 4] = r;
        }
    }
    {
        size_t base = (size_t)b * FEAT + (size_t)(e0 + 128) * NP;
        #pragma unroll
        for (int p4 = 0; p4 < 4; p4++) {
            float4 xr = *(const float4*)&x[base + p4 * 4];
            float4 r;
            r.x = o1[p4 * 4 + 0] * inv1 + xr.x;
            r.y = o1[p4 * 4 + 1] * inv1 + xr.y;
            r.z = o1[p4 * 4 + 2] * inv1 + xr.z;
            r.w = o1[p4 * 4 + 3] * inv1 + xr.w;
            *(float4*)&out[base + p4 * 4] = r;
        }
    }
}

// ---------------- launcher ----------------
extern "C" void kernel_launch(void* const* d_in, const int* in_sizes, int n_in,
                              void* d_out, int out_size) {
    const float* x     = (const float*)d_in[0];
    const float* WQ_w  = (const float*)d_in[1];
    const float* WQ_b  = (const float*)d_in[2];
    const float* WK_w  = (const float*)d_in[3];
    const float* WK_b  = (const float*)d_in[4];
    const float* WV_w  = (const float*)d_in[5];
    const float* WV_b  = (const float*)d_in[6];
    const float* gamma = (const float*)d_in[7];
    const float* beta  = (const float*)d_in[8];
    float* out = (float*)d_out;

    bn_pass1<<<dim3(FEAT / 256, RCHUNKS), 256>>>(x);
    wsplit<<<3 * DDIM * DDIM / 256, 256>>>(WQ_w, WK_w, WV_w);
    bn_pass2<<<FEAT / 256, 256>>>(gamma, beta);
    normalize_split<<<(BATCH * FEAT / 4) / 256, 256>>>(x);
    gemm3_mma<<<dim3(4, 512, 3), 256>>>(WQ_b, WK_b, WV_b);
    attn_k<<<BATCH, 128>>>(x, out);
}

// round 4
// speedup vs baseline: 1.2566x; 1.2566x over previous
#include <cuda_runtime.h>
#include <stdint.h>

// Problem constants
#define BATCH 4096
#define FEAT  4096
#define NP    16
#define DDIM  256
#define MROWS (BATCH * NP)   // 65536
#define EPS   1e-5f
#define INV_SCALE 0.0625f    // 1/sqrt(256)

// ---------------- device scratch ----------------
#define RCHUNKS 32
__device__ float g_psum[RCHUNKS * FEAT];
__device__ float g_psumsq[RCHUNKS * FEAT];
__device__ float g_scale[FEAT];
__device__ float g_shift[FEAT];
__device__ float g_q[(size_t)MROWS * DDIM];
__device__ float g_k[(size_t)MROWS * DDIM];
__device__ float g_v[(size_t)MROWS * DDIM];

__device__ __forceinline__ float f2tf32(float x) {
    uint32_t r;
    asm("cvt.rna.tf32.f32 %0, %1;" : "=r"(r) : "f"(x));
    return __uint_as_float(r);
}
__device__ __forceinline__ float2 bnsplit(float v, float sc, float sh) {
    float y = fmaf(v, sc, sh);
    float hi = f2tf32(y);
    return make_float2(hi, f2tf32(y - hi));
}
__device__ __forceinline__ float2 wsplit2(float v) {
    float hi = f2tf32(v);
    return make_float2(hi, f2tf32(v - hi));
}

#define MMA_OP(c, a0, a1, a2, a3, b0, b1)                                  \
    asm volatile(                                                          \
        "mma.sync.aligned.m16n8k8.row.col.f32.tf32.tf32.f32 "              \
        "{%0,%1,%2,%3}, {%4,%5,%6,%7}, {%8,%9}, {%0,%1,%2,%3};"            \
        : "+f"((c)[0]), "+f"((c)[1]), "+f"((c)[2]), "+f"((c)[3])           \
        : "r"(a0), "r"(a1), "r"(a2), "r"(a3), "r"(b0), "r"(b1))

// ---------------- BN pass 1 ----------------
__global__ void bn_pass1(const float* __restrict__ x) {
    int col = blockIdx.x * 256 + threadIdx.x;
    int r0  = blockIdx.y * (BATCH / RCHUNKS);
    float s = 0.f, ss = 0.f;
    #pragma unroll 4
    for (int r = 0; r < BATCH / RCHUNKS; r++) {
        float v = x[(size_t)(r0 + r) * FEAT + col];
        s += v; ss += v * v;
    }
    g_psum[blockIdx.y * FEAT + col]   = s;
    g_psumsq[blockIdx.y * FEAT + col] = ss;
}

// ---------------- BN pass 2 ----------------
__global__ void bn_pass2(const float* __restrict__ gamma,
                         const float* __restrict__ beta) {
    int col = blockIdx.x * blockDim.x + threadIdx.x;
    float s = 0.f, ss = 0.f;
    #pragma unroll
    for (int c = 0; c < RCHUNKS; c++) {
        s  += g_psum[c * FEAT + col];
        ss += g_psumsq[c * FEAT + col];
    }
    float mean = s * (1.f / BATCH);
    float var  = ss * (1.f / BATCH) - mean * mean;
    float rstd = rsqrtf(var + EPS);
    float a = rstd * gamma[col];
    g_scale[col] = a;
    g_shift[col] = beta[col] - mean * a;
}

// ---------------- mma.sync tf32-split QKV GEMM, BN fused on A ----------------
// grid (3, 512): blockIdx.x = weight, blockIdx.y = 128-row m-tile.
// 256 threads = 8 warps in 2(m) x 4(n); warp tile m64 x n64.
// K in 16 chunks of 16, double-buffered smem, pitch 20 float2 (conflict-free).
#define P2   20
#define A_F2 (128 * P2)                 // 2560 float2 per A stage
#define B_F2 (256 * P2)                 // 5120 float2 per B stage
#define SMEM_GEMM ((2 * A_F2 + 2 * B_F2) * 8)   // 122880 bytes

__global__ void __launch_bounds__(256, 1) gemm_mma(
    const float* __restrict__ x,
    const float* __restrict__ wq, const float* __restrict__ wk,
    const float* __restrict__ wv,
    const float* __restrict__ bq, const float* __restrict__ bk_,
    const float* __restrict__ bv)
{
    extern __shared__ float2 sm[];
    const int tid = threadIdx.x;
    const int w   = blockIdx.x;
    const int m0  = blockIdx.y * 128;

    const float* W    = (w == 0) ? wq : (w == 1) ? wk : wv;
    const float* bias = (w == 0) ? bq : (w == 1) ? bk_ : bv;
    float*       out  = (w == 0) ? g_q : (w == 1) ? g_k : g_v;

    const int lane = tid & 31, wid = tid >> 5;
    const int wm = wid >> 2;            // 0..1
    const int wn = wid & 3;             // 0..3
    const int g4 = lane >> 2, l4 = lane & 3;

    // load-side mapping
    const int arow = tid >> 1;          // 0..127
    const int akc  = (tid & 1) * 8;     // 0 / 8
    const int brow = tid;               // 0..255
    const float* asrc = x + (size_t)(m0 + arow) * DDIM;   // A[m][k] = x_flat[m*256+k]
    const float* bsrc = W + (size_t)brow * DDIM;
    const int fcb = (arow & 15) * 256;  // BN feature col base (m0 % 16 == 0)

    float acc[4][8][4];
    #pragma unroll
    for (int tm = 0; tm < 4; tm++)
        #pragma unroll
        for (int nt = 0; nt < 8; nt++)
            #pragma unroll
            for (int i = 0; i < 4; i++) acc[tm][nt][i] = 0.f;

    float4 pa0, pa1, pb0, pb1, pb2, pb3;

    auto LDG = [&](int c) {
        int kabs = c * 16;
        pa0 = *(const float4*)(asrc + kabs + akc);
        pa1 = *(const float4*)(asrc + kabs + akc + 4);
        pb0 = *(const float4*)(bsrc + kabs);
        pb1 = *(const float4*)(bsrc + kabs + 4);
        pb2 = *(const float4*)(bsrc + kabs + 8);
        pb3 = *(const float4*)(bsrc + kabs + 12);
    };

    auto CVT_STS = [&](int c, int st) {
        int kabs = c * 16;
        // ---- A: BN fuse + split ----
        const float4 sc0 = *(const float4*)(g_scale + fcb + kabs + akc);
        const float4 sc1 = *(const float4*)(g_scale + fcb + kabs + akc + 4);
        const float4 sh0 = *(const float4*)(g_shift + fcb + kabs + akc);
        const float4 sh1 = *(const float4*)(g_shift + fcb + kabs + akc + 4);
        float2 a0 = bnsplit(pa0.x, sc0.x, sh0.x);
        float2 a1 = bnsplit(pa0.y, sc0.y, sh0.y);
        float2 a2 = bnsplit(pa0.z, sc0.z, sh0.z);
        float2 a3 = bnsplit(pa0.w, sc0.w, sh0.w);
        float2 a4 = bnsplit(pa1.x, sc1.x, sh1.x);
        float2 a5 = bnsplit(pa1.y, sc1.y, sh1.y);
        float2 a6 = bnsplit(pa1.z, sc1.z, sh1.z);
        float2 a7 = bnsplit(pa1.w, sc1.w, sh1.w);
        float4* adst = (float4*)(sm + (size_t)st * A_F2 + arow * P2 + akc);
        adst[0] = make_float4(a0.x, a0.y, a1.x, a1.y);
        adst[1] = make_float4(a2.x, a2.y, a3.x, a3.y);
        adst[2] = make_float4(a4.x, a4.y, a5.x, a5.y);
        adst[3] = make_float4(a6.x, a6.y, a7.x, a7.y);
        // ---- B: split ----
        float2 b0 = wsplit2(pb0.x), b1 = wsplit2(pb0.y);
        float2 b2 = wsplit2(pb0.z), b3 = wsplit2(pb0.w);
        float2 b4 = wsplit2(pb1.x), b5 = wsplit2(pb1.y);
        float2 b6 = wsplit2(pb1.z), b7 = wsplit2(pb1.w);
        float2 b8 = wsplit2(pb2.x), b9 = wsplit2(pb2.y);
        float2 ba = wsplit2(pb2.z), bb = wsplit2(pb2.w);
        float2 bc = wsplit2(pb3.x), bd = wsplit2(pb3.y);
        float2 be = wsplit2(pb3.z), bf = wsplit2(pb3.w);
        float4* bdst = (float4*)(sm + 2 * A_F2 + (size_t)st * B_F2 + brow * P2);
        bdst[0] = make_float4(b0.x, b0.y, b1.x, b1.y);
        bdst[1] = make_float4(b2.x, b2.y, b3.x, b3.y);
        bdst[2] = make_float4(b4.x, b4.y, b5.x, b5.y);
        bdst[3] = make_float4(b6.x, b6.y, b7.x, b7.y);
        bdst[4] = make_float4(b8.x, b8.y, b9.x, b9.y);
        bdst[5] = make_float4(ba.x, ba.y, bb.x, bb.y);
        bdst[6] = make_float4(bc.x, bc.y, bd.x, bd.y);
        bdst[7] = make_float4(be.x, be.y, bf.x, bf.y);
    };

    auto MMA_CHUNK = [&](int st) {
        const float2* A0 = sm + (size_t)st * A_F2 + (wm * 64) * P2;
        const float2* B0 = sm + 2 * A_F2 + (size_t)st * B_F2 + (wn * 64) * P2;
        #pragma unroll
        for (int kk = 0; kk < 16; kk += 8) {
            float2 af[4][4];
            #pragma unroll
            for (int tm = 0; tm < 4; tm++) {
                int r = tm * 16 + g4;
                af[tm][0] = A0[r * P2 + kk + l4];
                af[tm][1] = A0[(r + 8) * P2 + kk + l4];
                af[tm][2] = A0[r * P2 + kk + l4 + 4];
                af[tm][3] = A0[(r + 8) * P2 + kk + l4 + 4];
            }
            #pragma unroll
            for (int nt = 0; nt < 8; nt++) {
                float2 fb0 = B0[(nt * 8 + g4) * P2 + kk + l4];
                float2 fb1 = B0[(nt * 8 + g4) * P2 + kk + l4 + 4];
                uint32_t bh0 = __float_as_uint(fb0.x), bl0 = __float_as_uint(fb0.y);
                uint32_t bh1 = __float_as_uint(fb1.x), bl1 = __float_as_uint(fb1.y);
                #pragma unroll
                for (int tm = 0; tm < 4; tm++) {
                    uint32_t ah0 = __float_as_uint(af[tm][0].x);
                    uint32_t ah1 = __float_as_uint(af[tm][1].x);
                    uint32_t ah2 = __float_as_uint(af[tm][2].x);
                    uint32_t ah3 = __float_as_uint(af[tm][3].x);
                    uint32_t al0 = __float_as_uint(af[tm][0].y);
                    uint32_t al1 = __float_as_uint(af[tm][1].y);
                    uint32_t al2 = __float_as_uint(af[tm][2].y);
                    uint32_t al3 = __float_as_uint(af[tm][3].y);
                    MMA_OP(acc[tm][nt], ah0, ah1, ah2, ah3, bh0, bh1);
                    MMA_OP(acc[tm][nt], ah0, ah1, ah2, ah3, bl0, bl1);
                    MMA_OP(acc[tm][nt], al0, al1, al2, al3, bh0, bh1);
                }
            }
        }
    };

    LDG(0);
    CVT_STS(0, 0);
    __syncthreads();
    #pragma unroll 1
    for (int c = 0; c < 16; c++) {
        if (c < 15) LDG(c + 1);
        MMA_CHUNK(c & 1);
        if (c < 15) {
            CVT_STS(c + 1, (c + 1) & 1);
            __syncthreads();
        }
    }

    // ---- epilogue: bias add + store ----
    const int rbase = m0 + wm * 64;
    const int cbase = wn * 64;
    #pragma unroll
    for (int tm = 0; tm < 4; tm++) {
        int row = rbase + tm * 16 + g4;
        #pragma unroll
        for (int nt = 0; nt < 8; nt++) {
            int col = cbase + nt * 8 + l4 * 2;
            float2 bb = *(const float2*)(bias + col);
            *(float2*)(out + (size_t)row * DDIM + col) =
                make_float2(acc[tm][nt][0] + bb.x, acc[tm][nt][1] + bb.y);
            *(float2*)(out + (size_t)(row + 8) * DDIM + col) =
                make_float2(acc[tm][nt][2] + bb.x, acc[tm][nt][3] + bb.y);
        }
    }
}

// ---------------- per-batch attention (unchanged) ----------------
__global__ void __launch_bounds__(128) attn_k(const float* __restrict__ x,
                                              float* __restrict__ out)
{
    __shared__ float Qs[NP * DDIM];
    __shared__ float Ks[NP * DDIM];
    __shared__ float Vs[NP * DDIM];

    int b = blockIdx.x;
    int tid = threadIdx.x;

    {
        const float4* qsrc = (const float4*)(g_q + (size_t)b * (NP * DDIM));
        const float4* ksrc = (const float4*)(g_k + (size_t)b * (NP * DDIM));
        const float4* vsrc = (const float4*)(g_v + (size_t)b * (NP * DDIM));
        float4* qd = (float4*)Qs; float4* kd = (float4*)Ks; float4* vd = (float4*)Vs;
        #pragma unroll
        for (int i = tid; i < NP * DDIM / 4; i += 128) {
            qd[i] = qsrc[i]; kd[i] = ksrc[i]; vd[i] = vsrc[i];
        }
    }
    __syncthreads();

    int e0 = tid;
    float q0[NP], q1[NP];
    #pragma unroll
    for (int p = 0; p < NP; p++) {
        q0[p] = Qs[p * DDIM + e0];
        q1[p] = Qs[p * DDIM + e0 + 128];
    }
    float o0[NP], o1[NP];
    #pragma unroll
    for (int p = 0; p < NP; p++) { o0[p] = 0.f; o1[p] = 0.f; }
    float s0 = 0.f, s1 = 0.f;

    const float4* K4 = (const float4*)Ks;
    const float4* V4 = (const float4*)Vs;

    for (int f4 = 0; f4 < DDIM / 4; f4++) {
        float d00 = 0.f, d01 = 0.f, d02 = 0.f, d03 = 0.f;
        float d10 = 0.f, d11 = 0.f, d12 = 0.f, d13 = 0.f;
        #pragma unroll
        for (int p = 0; p < NP; p++) {
            float4 kk = K4[p * (DDIM / 4) + f4];
            d00 += q0[p] * kk.x; d01 += q0[p] * kk.y;
            d02 += q0[p] * kk.z; d03 += q0[p] * kk.w;
            d10 += q1[p] * kk.x; d11 += q1[p] * kk.y;
            d12 += q1[p] * kk.z; d13 += q1[p] * kk.w;
        }
        float t00 = __expf(d00 * INV_SCALE), t01 = __expf(d01 * INV_SCALE);
        float t02 = __expf(d02 * INV_SCALE), t03 = __expf(d03 * INV_SCALE);
        float t10 = __expf(d10 * INV_SCALE), t11 = __expf(d11 * INV_SCALE);
        float t12 = __expf(d12 * INV_SCALE), t13 = __expf(d13 * INV_SCALE);
        s0 += (t00 + t01) + (t02 + t03);
        s1 += (t10 + t11) + (t12 + t13);
        #pragma unroll
        for (int p = 0; p < NP; p++) {
            float4 vv = V4[p * (DDIM / 4) + f4];
            o0[p] += t00 * vv.x + t01 * vv.y + t02 * vv.z + t03 * vv.w;
            o1[p] += t10 * vv.x + t11 * vv.y + t12 * vv.z + t13 * vv.w;
        }
    }

    float inv0 = 1.f / s0, inv1 = 1.f / s1;
    {
        size_t base = (size_t)b * FEAT + (size_t)e0 * NP;
        #pragma unroll
        for (int p4 = 0; p4 < 4; p4++) {
            float4 xr = *(const float4*)&x[base + p4 * 4];
            float4 r;
            r.x = o0[p4 * 4 + 0] * inv0 + xr.x;
            r.y = o0[p4 * 4 + 1] * inv0 + xr.y;
            r.z = o0[p4 * 4 + 2] * inv0 + xr.z;
            r.w = o0[p4 * 4 + 3] * inv0 + xr.w;
            *(float4*)&out[base + p4 * 4] = r;
        }
    }
    {
        size_t base = (size_t)b * FEAT + (size_t)(e0 + 128) * NP;
        #pragma unroll
        for (int p4 = 0; p4 < 4; p4++) {
            float4 xr = *(const float4*)&x[base + p4 * 4];
            float4 r;
            r.x = o1[p4 * 4 + 0] * inv1 + xr.x;
            r.y = o1[p4 * 4 + 1] * inv1 + xr.y;
            r.z = o1[p4 * 4 + 2] * inv1 + xr.z;
            r.w = o1[p4 * 4 + 3] * inv1 + xr.w;
            *(float4*)&out[base + p4 * 4] = r;
        }
    }
}

// ---------------- launcher ----------------
extern "C" void kernel_launch(void* const* d_in, const int* in_sizes, int n_in,
                              void* d_out, int out_size) {
    const float* x     = (const float*)d_in[0];
    const float* WQ_w  = (const float*)d_in[1];
    const float* WQ_b  = (const float*)d_in[2];
    const float* WK_w  = (const float*)d_in[3];
    const float* WK_b  = (const float*)d_in[4];
    const float* WV_w  = (const float*)d_in[5];
    const float* WV_b  = (const float*)d_in[6];
    const float* gamma = (const float*)d_in[7];
    const float* beta  = (const float*)d_in[8];
    float* out = (float*)d_out;

    cudaFuncSetAttribute(gemm_mma, cudaFuncAttributeMaxDynamicSharedMemorySize,
                         SMEM_GEMM);

    bn_pass1<<<dim3(FEAT / 256, RCHUNKS), 256>>>(x);
    bn_pass2<<<FEAT / 256, 256>>>(gamma, beta);
    gemm_mma<<<dim3(3, 512), 256, SMEM_GEMM>>>(x, WQ_w, WK_w, WV_w,
                                               WQ_b, WK_b, WV_b);
    attn_k<<<BATCH, 128>>>(x, out);
}

// round 5
// speedup vs baseline: 1.6495x; 1.3126x over previous
#include <cuda_runtime.h>
#include <stdint.h>

// Problem constants
#define BATCH 4096
#define FEAT  4096
#define NP    16
#define DDIM  256
#define MROWS (BATCH * NP)   // 65536
#define EPS   1e-5f
#define INV_SCALE 0.0625f    // 1/sqrt(256)

// ---------------- device scratch ----------------
#define RCHUNKS 32
__device__ float g_psum[RCHUNKS * FEAT];
__device__ float g_psumsq[RCHUNKS * FEAT];
__device__ float g_scale[FEAT];
__device__ float g_shift[FEAT];
__device__ float g_q[(size_t)MROWS * DDIM];
__device__ float g_k[(size_t)MROWS * DDIM];
__device__ float g_v[(size_t)MROWS * DDIM];

// bf16 2-way split of a fp32 pair, packed for mma: returns (hi_pair, lo_pair)
// where each pair = bf16x2 {low half = y0, high half = y1}.
__device__ __forceinline__ uint2 bfsplit2(float y0, float y1) {
    uint32_t hi;
    asm("cvt.rn.bf16x2.f32 %0, %1, %2;" : "=r"(hi) : "f"(y1), "f"(y0));
    float h0 = __uint_as_float(hi << 16);            // bf16->f32 == top-16 bits
    float h1 = __uint_as_float(hi & 0xffff0000u);
    uint32_t lo;
    asm("cvt.rn.bf16x2.f32 %0, %1, %2;" : "=r"(lo) : "f"(y1 - h1), "f"(y0 - h0));
    return make_uint2(hi, lo);
}

#define MMA_BF16(c, a0, a1, a2, a3, b0, b1)                                \
    asm volatile(                                                          \
        "mma.sync.aligned.m16n8k16.row.col.f32.bf16.bf16.f32 "             \
        "{%0,%1,%2,%3}, {%4,%5,%6,%7}, {%8,%9}, {%0,%1,%2,%3};"            \
        : "+f"((c)[0]), "+f"((c)[1]), "+f"((c)[2]), "+f"((c)[3])           \
        : "r"(a0), "r"(a1), "r"(a2), "r"(a3), "r"(b0), "r"(b1))

// ---------------- BN pass 1 ----------------
__global__ void bn_pass1(const float* __restrict__ x) {
    int col = blockIdx.x * 256 + threadIdx.x;
    int r0  = blockIdx.y * (BATCH / RCHUNKS);
    float s = 0.f, ss = 0.f;
    #pragma unroll 4
    for (int r = 0; r < BATCH / RCHUNKS; r++) {
        float v = x[(size_t)(r0 + r) * FEAT + col];
        s += v; ss += v * v;
    }
    g_psum[blockIdx.y * FEAT + col]   = s;
    g_psumsq[blockIdx.y * FEAT + col] = ss;
}

// ---------------- BN pass 2 ----------------
__global__ void bn_pass2(const float* __restrict__ gamma,
                         const float* __restrict__ beta) {
    int col = blockIdx.x * blockDim.x + threadIdx.x;
    float s = 0.f, ss = 0.f;
    #pragma unroll
    for (int c = 0; c < RCHUNKS; c++) {
        s  += g_psum[c * FEAT + col];
        ss += g_psumsq[c * FEAT + col];
    }
    float mean = s * (1.f / BATCH);
    float var  = ss * (1.f / BATCH) - mean * mean;
    float rstd = rsqrtf(var + EPS);
    float a = rstd * gamma[col];
    g_scale[col] = a;
    g_shift[col] = beta[col] - mean * a;
}

// ---------------- bf16-split QKV GEMM (m16n8k16), BN fused on A ------------
// grid (3, 512): blockIdx.x = weight, blockIdx.y = 128-row m-tile.
// 256 threads = 8 warps in 2(m) x 4(n); warp tile m64 x n64.
// K in 16 chunks of 16 (1 mma k-step each), double-buffered smem.
// smem rows: 8 used uint2 (hi_pair, lo_pair per k-pair) + 4 pad = pitch 12.
#define PA   12
#define A_U2 (128 * PA)                 // uint2 per A stage
#define B_U2 (256 * PA)
#define SMEM_GEMM ((2 * A_U2 + 2 * B_U2) * 8)   // 73728 bytes

__global__ void __launch_bounds__(256, 1) gemm_mma(
    const float* __restrict__ x,
    const float* __restrict__ wq, const float* __restrict__ wk,
    const float* __restrict__ wv,
    const float* __restrict__ bq, const float* __restrict__ bk_,
    const float* __restrict__ bv)
{
    extern __shared__ uint2 sm[];
    const int tid = threadIdx.x;
    const int w   = blockIdx.x;
    const int m0  = blockIdx.y * 128;

    const float* W    = (w == 0) ? wq : (w == 1) ? wk : wv;
    const float* bias = (w == 0) ? bq : (w == 1) ? bk_ : bv;
    float*       out  = (w == 0) ? g_q : (w == 1) ? g_k : g_v;

    const int lane = tid & 31, wid = tid >> 5;
    const int wm = wid >> 2;            // 0..1
    const int wn = wid & 3;             // 0..3
    const int g4 = lane >> 2, l4 = lane & 3;

    // load-side mapping
    const int arow = tid >> 1;          // 0..127
    const int akc  = (tid & 1) * 8;     // element offset 0 / 8
    const int apb  = (tid & 1) * 4;     // pair offset 0 / 4
    const int brow = tid;               // 0..255
    const float* asrc = x + (size_t)(m0 + arow) * DDIM;
    const float* bsrc = W + (size_t)brow * DDIM;
    const int fcb = (arow & 15) * 256;  // BN feature col base

    float acc[4][8][4];
    #pragma unroll
    for (int tm = 0; tm < 4; tm++)
        #pragma unroll
        for (int nt = 0; nt < 8; nt++)
            #pragma unroll
            for (int i = 0; i < 4; i++) acc[tm][nt][i] = 0.f;

    float4 pa0, pa1, pb0, pb1, pb2, pb3;

    auto LDG = [&](int c) {
        int kabs = c * 16;
        pa0 = *(const float4*)(asrc + kabs + akc);
        pa1 = *(const float4*)(asrc + kabs + akc + 4);
        pb0 = *(const float4*)(bsrc + kabs);
        pb1 = *(const float4*)(bsrc + kabs + 4);
        pb2 = *(const float4*)(bsrc + kabs + 8);
        pb3 = *(const float4*)(bsrc + kabs + 12);
    };

    auto CVT_STS = [&](int c, int st) {
        int kabs = c * 16;
        // ---- A: BN fuse + bf16 split ----
        const float4 sc0 = *(const float4*)(g_scale + fcb + kabs + akc);
        const float4 sc1 = *(const float4*)(g_scale + fcb + kabs + akc + 4);
        const float4 sh0 = *(const float4*)(g_shift + fcb + kabs + akc);
        const float4 sh1 = *(const float4*)(g_shift + fcb + kabs + akc + 4);
        float y0 = fmaf(pa0.x, sc0.x, sh0.x);
        float y1 = fmaf(pa0.y, sc0.y, sh0.y);
        float y2 = fmaf(pa0.z, sc0.z, sh0.z);
        float y3 = fmaf(pa0.w, sc0.w, sh0.w);
        float y4 = fmaf(pa1.x, sc1.x, sh1.x);
        float y5 = fmaf(pa1.y, sc1.y, sh1.y);
        float y6 = fmaf(pa1.z, sc1.z, sh1.z);
        float y7 = fmaf(pa1.w, sc1.w, sh1.w);
        uint2* adst = sm + (size_t)st * A_U2 + arow * PA + apb;
        adst[0] = bfsplit2(y0, y1);
        adst[1] = bfsplit2(y2, y3);
        adst[2] = bfsplit2(y4, y5);
        adst[3] = bfsplit2(y6, y7);
        // ---- B: bf16 split ----
        uint2* bdst = sm + 2 * A_U2 + (size_t)st * B_U2 + brow * PA;
        bdst[0] = bfsplit2(pb0.x, pb0.y);
        bdst[1] = bfsplit2(pb0.z, pb0.w);
        bdst[2] = bfsplit2(pb1.x, pb1.y);
        bdst[3] = bfsplit2(pb1.z, pb1.w);
        bdst[4] = bfsplit2(pb2.x, pb2.y);
        bdst[5] = bfsplit2(pb2.z, pb2.w);
        bdst[6] = bfsplit2(pb3.x, pb3.y);
        bdst[7] = bfsplit2(pb3.z, pb3.w);
    };

    auto MMA_CHUNK = [&](int st) {
        const uint2* A0 = sm + (size_t)st * A_U2 + (wm * 64) * PA;
        const uint2* B0 = sm + 2 * A_U2 + (size_t)st * B_U2 + (wn * 64) * PA;
        uint2 af[4][4];
        #pragma unroll
        for (int tm = 0; tm < 4; tm++) {
            int r = tm * 16 + g4;
            af[tm][0] = A0[r * PA + l4];
            af[tm][1] = A0[(r + 8) * PA + l4];
            af[tm][2] = A0[r * PA + l4 + 4];
            af[tm][3] = A0[(r + 8) * PA + l4 + 4];
        }
        #pragma unroll
        for (int nt = 0; nt < 8; nt++) {
            uint2 fb0 = B0[(nt * 8 + g4) * PA + l4];
            uint2 fb1 = B0[(nt * 8 + g4) * PA + l4 + 4];
            #pragma unroll
            for (int tm = 0; tm < 4; tm++) {
                // hi*hi
                MMA_BF16(acc[tm][nt], af[tm][0].x, af[tm][1].x,
                         af[tm][2].x, af[tm][3].x, fb0.x, fb1.x);
                // hi*lo
                MMA_BF16(acc[tm][nt], af[tm][0].x, af[tm][1].x,
                         af[tm][2].x, af[tm][3].x, fb0.y, fb1.y);
                // lo*hi
                MMA_BF16(acc[tm][nt], af[tm][0].y, af[tm][1].y,
                         af[tm][2].y, af[tm][3].y, fb0.x, fb1.x);
            }
        }
    };

    LDG(0);
    CVT_STS(0, 0);
    __syncthreads();
    #pragma unroll 1
    for (int c = 0; c < 16; c++) {
        if (c < 15) LDG(c + 1);
        MMA_CHUNK(c & 1);
        if (c < 15) {
            CVT_STS(c + 1, (c + 1) & 1);
            __syncthreads();
        }
    }

    // ---- epilogue: bias add + store ----
    const int rbase = m0 + wm * 64;
    const int cbase = wn * 64;
    #pragma unroll
    for (int tm = 0; tm < 4; tm++) {
        int row = rbase + tm * 16 + g4;
        #pragma unroll
        for (int nt = 0; nt < 8; nt++) {
            int col = cbase + nt * 8 + l4 * 2;
            float2 bb = *(const float2*)(bias + col);
            *(float2*)(out + (size_t)row * DDIM + col) =
                make_float2(acc[tm][nt][0] + bb.x, acc[tm][nt][1] + bb.y);
            *(float2*)(out + (size_t)(row + 8) * DDIM + col) =
                make_float2(acc[tm][nt][2] + bb.x, acc[tm][nt][3] + bb.y);
        }
    }
}

// ---------------- per-batch attention (unchanged) ----------------
__global__ void __launch_bounds__(128) attn_k(const float* __restrict__ x,
                                              float* __restrict__ out)
{
    __shared__ float Qs[NP * DDIM];
    __shared__ float Ks[NP * DDIM];
    __shared__ float Vs[NP * DDIM];

    int b = blockIdx.x;
    int tid = threadIdx.x;

    {
        const float4* qsrc = (const float4*)(g_q + (size_t)b * (NP * DDIM));
        const float4* ksrc = (const float4*)(g_k + (size_t)b * (NP * DDIM));
        const float4* vsrc = (const float4*)(g_v + (size_t)b * (NP * DDIM));
        float4* qd = (float4*)Qs; float4* kd = (float4*)Ks; float4* vd = (float4*)Vs;
        #pragma unroll
        for (int i = tid; i < NP * DDIM / 4; i += 128) {
            qd[i] = qsrc[i]; kd[i] = ksrc[i]; vd[i] = vsrc[i];
        }
    }
    __syncthreads();

    int e0 = tid;
    float q0[NP], q1[NP];
    #pragma unroll
    for (int p = 0; p < NP; p++) {
        q0[p] = Qs[p * DDIM + e0];
        q1[p] = Qs[p * DDIM + e0 + 128];
    }
    float o0[NP], o1[NP];
    #pragma unroll
    for (int p = 0; p < NP; p++) { o0[p] = 0.f; o1[p] = 0.f; }
    float s0 = 0.f, s1 = 0.f;

    const float4* K4 = (const float4*)Ks;
    const float4* V4 = (const float4*)Vs;

    for (int f4 = 0; f4 < DDIM / 4; f4++) {
        float d00 = 0.f, d01 = 0.f, d02 = 0.f, d03 = 0.f;
        float d10 = 0.f, d11 = 0.f, d12 = 0.f, d13 = 0.f;
        #pragma unroll
        for (int p = 0; p < NP; p++) {
            float4 kk = K4[p * (DDIM / 4) + f4];
            d00 += q0[p] * kk.x; d01 += q0[p] * kk.y;
            d02 += q0[p] * kk.z; d03 += q0[p] * kk.w;
            d10 += q1[p] * kk.x; d11 += q1[p] * kk.y;
            d12 += q1[p] * kk.z; d13 += q1[p] * kk.w;
        }
        float t00 = __expf(d00 * INV_SCALE), t01 = __expf(d01 * INV_SCALE);
        float t02 = __expf(d02 * INV_SCALE), t03 = __expf(d03 * INV_SCALE);
        float t10 = __expf(d10 * INV_SCALE), t11 = __expf(d11 * INV_SCALE);
        float t12 = __expf(d12 * INV_SCALE), t13 = __expf(d13 * INV_SCALE);
        s0 += (t00 + t01) + (t02 + t03);
        s1 += (t10 + t11) + (t12 + t13);
        #pragma unroll
        for (int p = 0; p < NP; p++) {
            float4 vv = V4[p * (DDIM / 4) + f4];
            o0[p] += t00 * vv.x + t01 * vv.y + t02 * vv.z + t03 * vv.w;
            o1[p] += t10 * vv.x + t11 * vv.y + t12 * vv.z + t13 * vv.w;
        }
    }

    float inv0 = 1.f / s0, inv1 = 1.f / s1;
    {
        size_t base = (size_t)b * FEAT + (size_t)e0 * NP;
        #pragma unroll
        for (int p4 = 0; p4 < 4; p4++) {
            float4 xr = *(const float4*)&x[base + p4 * 4];
            float4 r;
            r.x = o0[p4 * 4 + 0] * inv0 + xr.x;
            r.y = o0[p4 * 4 + 1] * inv0 + xr.y;
            r.z = o0[p4 * 4 + 2] * inv0 + xr.z;
            r.w = o0[p4 * 4 + 3] * inv0 + xr.w;
            *(float4*)&out[base + p4 * 4] = r;
        }
    }
    {
        size_t base = (size_t)b * FEAT + (size_t)(e0 + 128) * NP;
        #pragma unroll
        for (int p4 = 0; p4 < 4; p4++) {
            float4 xr = *(const float4*)&x[base + p4 * 4];
            float4 r;
            r.x = o1[p4 * 4 + 0] * inv1 + xr.x;
            r.y = o1[p4 * 4 + 1] * inv1 + xr.y;
            r.z = o1[p4 * 4 + 2] * inv1 + xr.z;
            r.w = o1[p4 * 4 + 3] * inv1 + xr.w;
            *(float4*)&out[base + p4 * 4] = r;
        }
    }
}

// ---------------- launcher ----------------
extern "C" void kernel_launch(void* const* d_in, const int* in_sizes, int n_in,
                              void* d_out, int out_size) {
    const float* x     = (const float*)d_in[0];
    const float* WQ_w  = (const float*)d_in[1];
    const float* WQ_b  = (const float*)d_in[2];
    const float* WK_w  = (const float*)d_in[3];
    const float* WK_b  = (const float*)d_in[4];
    const float* WV_w  = (const float*)d_in[5];
    const float* WV_b  = (const float*)d_in[6];
    const float* gamma = (const float*)d_in[7];
    const float* beta  = (const float*)d_in[8];
    float* out = (float*)d_out;

    cudaFuncSetAttribute(gemm_mma, cudaFuncAttributeMaxDynamicSharedMemorySize,
                         SMEM_GEMM);

    bn_pass1<<<dim3(FEAT / 256, RCHUNKS), 256>>>(x);
    bn_pass2<<<FEAT / 256, 256>>>(gamma, beta);
    gemm_mma<<<dim3(3, 512), 256, SMEM_GEMM>>>(x, WQ_w, WK_w, WV_w,
                                               WQ_b, WK_b, WV_b);
    attn_k<<<BATCH, 128>>>(x, out);
}

// round 6
// speedup vs baseline: 1.9070x; 1.1561x over previous
#include <cuda_runtime.h>
#include <stdint.h>

// Problem constants
#define BATCH 4096
#define FEAT  4096
#define NP    16
#define DDIM  256
#define MROWS (BATCH * NP)   // 65536
#define EPS   1e-5f
#define INV_SCALE 0.0625f    // 1/sqrt(256)

// ---------------- device scratch ----------------
#define RCHUNKS 32
__device__ float g_psum[RCHUNKS * FEAT];
__device__ float g_psumsq[RCHUNKS * FEAT];
__device__ float g_scale[FEAT];
__device__ float g_shift[FEAT];
__device__ float g_q[(size_t)MROWS * DDIM];
__device__ float g_k[(size_t)MROWS * DDIM];
__device__ float g_v[(size_t)MROWS * DDIM];

// bf16 2-way split of a fp32 pair, packed for mma: (hi_pair, lo_pair),
// lower half = y0, upper half = y1.
__device__ __forceinline__ uint2 bfsplit2(float y0, float y1) {
    uint32_t hi;
    asm("cvt.rn.bf16x2.f32 %0, %1, %2;" : "=r"(hi) : "f"(y1), "f"(y0));
    float h0 = __uint_as_float(hi << 16);
    float h1 = __uint_as_float(hi & 0xffff0000u);
    uint32_t lo;
    asm("cvt.rn.bf16x2.f32 %0, %1, %2;" : "=r"(lo) : "f"(y1 - h1), "f"(y0 - h0));
    return make_uint2(hi, lo);
}
__device__ __forceinline__ uint32_t bfpack(float y0, float y1) {
    uint32_t h;
    asm("cvt.rn.bf16x2.f32 %0, %1, %2;" : "=r"(h) : "f"(y1), "f"(y0));
    return h;
}

#define MMA_BF16(c, a0, a1, a2, a3, b0, b1)                                \
    asm volatile(                                                          \
        "mma.sync.aligned.m16n8k16.row.col.f32.bf16.bf16.f32 "             \
        "{%0,%1,%2,%3}, {%4,%5,%6,%7}, {%8,%9}, {%0,%1,%2,%3};"            \
        : "+f"((c)[0]), "+f"((c)[1]), "+f"((c)[2]), "+f"((c)[3])           \
        : "r"(a0), "r"(a1), "r"(a2), "r"(a3), "r"(b0), "r"(b1))

// ---------------- BN pass 1 ----------------
__global__ void bn_pass1(const float* __restrict__ x) {
    int col = blockIdx.x * 256 + threadIdx.x;
    int r0  = blockIdx.y * (BATCH / RCHUNKS);
    float s = 0.f, ss = 0.f;
    #pragma unroll 4
    for (int r = 0; r < BATCH / RCHUNKS; r++) {
        float v = x[(size_t)(r0 + r) * FEAT + col];
        s += v; ss += v * v;
    }
    g_psum[blockIdx.y * FEAT + col]   = s;
    g_psumsq[blockIdx.y * FEAT + col] = ss;
}

// ---------------- BN pass 2 ----------------
__global__ void bn_pass2(const float* __restrict__ gamma,
                         const float* __restrict__ beta) {
    int col = blockIdx.x * blockDim.x + threadIdx.x;
    float s = 0.f, ss = 0.f;
    #pragma unroll
    for (int c = 0; c < RCHUNKS; c++) {
        s  += g_psum[c * FEAT + col];
        ss += g_psumsq[c * FEAT + col];
    }
    float mean = s * (1.f / BATCH);
    float var  = ss * (1.f / BATCH) - mean * mean;
    float rstd = rsqrtf(var + EPS);
    float a = rstd * gamma[col];
    g_scale[col] = a;
    g_shift[col] = beta[col] - mean * a;
}

// ---------------- bf16-split QKV GEMM (unchanged from round 5) -------------
#define PA   12
#define A_U2 (128 * PA)
#define B_U2 (256 * PA)
#define SMEM_GEMM ((2 * A_U2 + 2 * B_U2) * 8)   // 73728 bytes

__global__ void __launch_bounds__(256, 1) gemm_mma(
    const float* __restrict__ x,
    const float* __restrict__ wq, const float* __restrict__ wk,
    const float* __restrict__ wv,
    const float* __restrict__ bq, const float* __restrict__ bk_,
    const float* __restrict__ bv)
{
    extern __shared__ uint2 sm[];
    const int tid = threadIdx.x;
    const int w   = blockIdx.x;
    const int m0  = blockIdx.y * 128;

    const float* W    = (w == 0) ? wq : (w == 1) ? wk : wv;
    const float* bias = (w == 0) ? bq : (w == 1) ? bk_ : bv;
    float*       out  = (w == 0) ? g_q : (w == 1) ? g_k : g_v;

    const int lane = tid & 31, wid = tid >> 5;
    const int wm = wid >> 2;
    const int wn = wid & 3;
    const int g4 = lane >> 2, l4 = lane & 3;

    const int arow = tid >> 1;
    const int akc  = (tid & 1) * 8;
    const int apb  = (tid & 1) * 4;
    const int brow = tid;
    const float* asrc = x + (size_t)(m0 + arow) * DDIM;
    const float* bsrc = W + (size_t)brow * DDIM;
    const int fcb = (arow & 15) * 256;

    float acc[4][8][4];
    #pragma unroll
    for (int tm = 0; tm < 4; tm++)
        #pragma unroll
        for (int nt = 0; nt < 8; nt++)
            #pragma unroll
            for (int i = 0; i < 4; i++) acc[tm][nt][i] = 0.f;

    float4 pa0, pa1, pb0, pb1, pb2, pb3;

    auto LDG = [&](int c) {
        int kabs = c * 16;
        pa0 = *(const float4*)(asrc + kabs + akc);
        pa1 = *(const float4*)(asrc + kabs + akc + 4);
        pb0 = *(const float4*)(bsrc + kabs);
        pb1 = *(const float4*)(bsrc + kabs + 4);
        pb2 = *(const float4*)(bsrc + kabs + 8);
        pb3 = *(const float4*)(bsrc + kabs + 12);
    };

    auto CVT_STS = [&](int c, int st) {
        int kabs = c * 16;
        const float4 sc0 = *(const float4*)(g_scale + fcb + kabs + akc);
        const float4 sc1 = *(const float4*)(g_scale + fcb + kabs + akc + 4);
        const float4 sh0 = *(const float4*)(g_shift + fcb + kabs + akc);
        const float4 sh1 = *(const float4*)(g_shift + fcb + kabs + akc + 4);
        float y0 = fmaf(pa0.x, sc0.x, sh0.x);
        float y1 = fmaf(pa0.y, sc0.y, sh0.y);
        float y2 = fmaf(pa0.z, sc0.z, sh0.z);
        float y3 = fmaf(pa0.w, sc0.w, sh0.w);
        float y4 = fmaf(pa1.x, sc1.x, sh1.x);
        float y5 = fmaf(pa1.y, sc1.y, sh1.y);
        float y6 = fmaf(pa1.z, sc1.z, sh1.z);
        float y7 = fmaf(pa1.w, sc1.w, sh1.w);
        uint2* adst = sm + (size_t)st * A_U2 + arow * PA + apb;
        adst[0] = bfsplit2(y0, y1);
        adst[1] = bfsplit2(y2, y3);
        adst[2] = bfsplit2(y4, y5);
        adst[3] = bfsplit2(y6, y7);
        uint2* bdst = sm + 2 * A_U2 + (size_t)st * B_U2 + brow * PA;
        bdst[0] = bfsplit2(pb0.x, pb0.y);
        bdst[1] = bfsplit2(pb0.z, pb0.w);
        bdst[2] = bfsplit2(pb1.x, pb1.y);
        bdst[3] = bfsplit2(pb1.z, pb1.w);
        bdst[4] = bfsplit2(pb2.x, pb2.y);
        bdst[5] = bfsplit2(pb2.z, pb2.w);
        bdst[6] = bfsplit2(pb3.x, pb3.y);
        bdst[7] = bfsplit2(pb3.z, pb3.w);
    };

    auto MMA_CHUNK = [&](int st) {
        const uint2* A0 = sm + (size_t)st * A_U2 + (wm * 64) * PA;
        const uint2* B0 = sm + 2 * A_U2 + (size_t)st * B_U2 + (wn * 64) * PA;
        uint2 af[4][4];
        #pragma unroll
        for (int tm = 0; tm < 4; tm++) {
            int r = tm * 16 + g4;
            af[tm][0] = A0[r * PA + l4];
            af[tm][1] = A0[(r + 8) * PA + l4];
            af[tm][2] = A0[r * PA + l4 + 4];
            af[tm][3] = A0[(r + 8) * PA + l4 + 4];
        }
        #pragma unroll
        for (int nt = 0; nt < 8; nt++) {
            uint2 fb0 = B0[(nt * 8 + g4) * PA + l4];
            uint2 fb1 = B0[(nt * 8 + g4) * PA + l4 + 4];
            #pragma unroll
            for (int tm = 0; tm < 4; tm++) {
                MMA_BF16(acc[tm][nt], af[tm][0].x, af[tm][1].x,
                         af[tm][2].x, af[tm][3].x, fb0.x, fb1.x);
                MMA_BF16(acc[tm][nt], af[tm][0].x, af[tm][1].x,
                         af[tm][2].x, af[tm][3].x, fb0.y, fb1.y);
                MMA_BF16(acc[tm][nt], af[tm][0].y, af[tm][1].y,
                         af[tm][2].y, af[tm][3].y, fb0.x, fb1.x);
            }
        }
    };

    LDG(0);
    CVT_STS(0, 0);
    __syncthreads();
    #pragma unroll 1
    for (int c = 0; c < 16; c++) {
        if (c < 15) LDG(c + 1);
        MMA_CHUNK(c & 1);
        if (c < 15) {
            CVT_STS(c + 1, (c + 1) & 1);
            __syncthreads();
        }
    }

    const int rbase = m0 + wm * 64;
    const int cbase = wn * 64;
    #pragma unroll
    for (int tm = 0; tm < 4; tm++) {
        int row = rbase + tm * 16 + g4;
        #pragma unroll
        for (int nt = 0; nt < 8; nt++) {
            int col = cbase + nt * 8 + l4 * 2;
            float2 bb = *(const float2*)(bias + col);
            *(float2*)(out + (size_t)row * DDIM + col) =
                make_float2(acc[tm][nt][0] + bb.x, acc[tm][nt][1] + bb.y);
            *(float2*)(out + (size_t)(row + 8) * DDIM + col) =
                make_float2(acc[tm][nt][2] + bb.x, acc[tm][nt][3] + bb.y);
        }
    }
}

// ---------------- tensor-core attention ----------------
// 1 CTA per batch, 256 threads = 8 warps; warp w owns e-rows [w*32, w*32+32).
// S = Q^T K (k = p = 16, one mma k-step), 3-term bf16 split.
// exp in-register, P repacked to A-frags (split), AV with V_hi (2 terms).
#define APITCH 12                        // uint2 per row (Qt / Kt)
#define VPITCH 132                       // uint32 per row (Vh)
#define SMEM_ATTN (2 * 256 * APITCH * 8 + 16 * VPITCH * 4)   // 57600 B

__global__ void __launch_bounds__(256, 1) attn_tc(const float* __restrict__ x,
                                                  float* __restrict__ out)
{
    extern __shared__ uint2 smq[];
    uint2* Qt = smq;                          // [e][p-pair] (hi,lo)
    uint2* Kt = smq + 256 * APITCH;           // [f][p-pair] (hi,lo)
    uint32_t* Vh = (uint32_t*)(smq + 2 * 256 * APITCH);  // [p][f-pair] hi

    const int b = blockIdx.x;
    const int tid = threadIdx.x;
    const int lane = tid & 31, wid = tid >> 5;
    const int g4 = lane >> 2, l4 = lane & 3;

    // ---- load + transpose + split Q and K: thread = (p-pair j, 8 e/f) ----
    {
        const int j  = tid & 7;
        const int e0 = (tid >> 3) * 8;
        const float* q0p = g_q + (size_t)b * 4096 + (2 * j) * 256 + e0;
        const float* k0p = g_k + (size_t)b * 4096 + (2 * j) * 256 + e0;
        float4 qa = *(const float4*)q0p;
        float4 qb = *(const float4*)(q0p + 4);
        float4 qc = *(const float4*)(q0p + 256);
        float4 qd = *(const float4*)(q0p + 260);
        float q0[8] = {qa.x, qa.y, qa.z, qa.w, qb.x, qb.y, qb.z, qb.w};
        float q1[8] = {qc.x, qc.y, qc.z, qc.w, qd.x, qd.y, qd.z, qd.w};
        #pragma unroll
        for (int i = 0; i < 8; i++)
            Qt[(e0 + i) * APITCH + j] = bfsplit2(q0[i], q1[i]);
        float4 ka = *(const float4*)k0p;
        float4 kb = *(const float4*)(k0p + 4);
        float4 kc = *(const float4*)(k0p + 256);
        float4 kd = *(const float4*)(k0p + 260);
        float k0[8] = {ka.x, ka.y, ka.z, ka.w, kb.x, kb.y, kb.z, kb.w};
        float k1[8] = {kc.x, kc.y, kc.z, kc.w, kd.x, kd.y, kd.z, kd.w};
        #pragma unroll
        for (int i = 0; i < 8; i++)
            Kt[(e0 + i) * APITCH + j] = bfsplit2(k0[i], k1[i]);
    }
    // ---- V: [p][f-pair] hi only ----
    {
        const int p  = tid >> 4;
        const int fq = (tid & 15) * 16;
        const float* vp = g_v + (size_t)b * 4096 + p * 256 + fq;
        #pragma unroll
        for (int h = 0; h < 2; h++) {
            float4 v0 = *(const float4*)(vp + h * 8);
            float4 v1 = *(const float4*)(vp + h * 8 + 4);
            uint32_t* d = Vh + p * VPITCH + (fq >> 1) + h * 4;
            d[0] = bfpack(v0.x, v0.y);
            d[1] = bfpack(v0.z, v0.w);
            d[2] = bfpack(v1.x, v1.y);
            d[3] = bfpack(v1.z, v1.w);
        }
    }
    __syncthreads();

    // ---- persistent Q fragments ----
    uint2 af[2][4];
    #pragma unroll
    for (int tm = 0; tm < 2; tm++) {
        int eb = wid * 32 + tm * 16;
        af[tm][0] = Qt[(eb + g4) * APITCH + l4];
        af[tm][1] = Qt[(eb + g4 + 8) * APITCH + l4];
        af[tm][2] = Qt[(eb + g4) * APITCH + l4 + 4];
        af[tm][3] = Qt[(eb + g4 + 8) * APITCH + l4 + 4];
    }

    float av[2][2][4];
    #pragma unroll
    for (int tm = 0; tm < 2; tm++)
        #pragma unroll
        for (int np = 0; np < 2; np++)
            #pragma unroll
            for (int i = 0; i < 4; i++) av[tm][np][i] = 0.f;
    float srow[2][2] = {{0.f, 0.f}, {0.f, 0.f}};

    #pragma unroll
    for (int fc = 0; fc < 256; fc += 64) {
        // ---- S chunk: 2 m-tiles x 8 n-tiles, 3-term split ----
        float E[2][8][4];
        #pragma unroll
        for (int nt = 0; nt < 8; nt++) {
            int f = fc + nt * 8 + g4;
            uint2 kb0 = Kt[f * APITCH + l4];
            uint2 kb1 = Kt[f * APITCH + l4 + 4];
            #pragma unroll
            for (int tm = 0; tm < 2; tm++) {
                float* c = E[tm][nt];
                c[0] = c[1] = c[2] = c[3] = 0.f;
                MMA_BF16(c, af[tm][0].x, af[tm][1].x, af[tm][2].x, af[tm][3].x,
                         kb0.x, kb1.x);
                MMA_BF16(c, af[tm][0].x, af[tm][1].x, af[tm][2].x, af[tm][3].x,
                         kb0.y, kb1.y);
                MMA_BF16(c, af[tm][0].y, af[tm][1].y, af[tm][2].y, af[tm][3].y,
                         kb0.x, kb1.x);
            }
        }
        // ---- exp + row sums ----
        #pragma unroll
        for (int tm = 0; tm < 2; tm++)
            #pragma unroll
            for (int nt = 0; nt < 8; nt++) {
                float* c = E[tm][nt];
                c[0] = __expf(c[0] * INV_SCALE);
                c[1] = __expf(c[1] * INV_SCALE);
                c[2] = __expf(c[2] * INV_SCALE);
                c[3] = __expf(c[3] * INV_SCALE);
                srow[tm][0] += c[0] + c[1];
                srow[tm][1] += c[2] + c[3];
            }
        // ---- AV: P (split) x V_hi ----
        #pragma unroll
        for (int s = 0; s < 4; s++) {
            uint32_t vb0[2], vb1[2];
            #pragma unroll
            for (int np = 0; np < 2; np++) {
                const uint32_t* vr = Vh + (np * 8 + g4) * VPITCH + (fc >> 1) + s * 8;
                vb0[np] = vr[l4];
                vb1[np] = vr[l4 + 4];
            }
            #pragma unroll
            for (int tm = 0; tm < 2; tm++) {
                uint2 a0 = bfsplit2(E[tm][2 * s][0], E[tm][2 * s][1]);
                uint2 a1 = bfsplit2(E[tm][2 * s][2], E[tm][2 * s][3]);
                uint2 a2 = bfsplit2(E[tm][2 * s + 1][0], E[tm][2 * s + 1][1]);
                uint2 a3 = bfsplit2(E[tm][2 * s + 1][2], E[tm][2 * s + 1][3]);
                #pragma unroll
                for (int np = 0; np < 2; np++) {
                    MMA_BF16(av[tm][np], a0.x, a1.x, a2.x, a3.x, vb0[np], vb1[np]);
                    MMA_BF16(av[tm][np], a0.y, a1.y, a2.y, a3.y, vb0[np], vb1[np]);
                }
            }
        }
    }

    // ---- epilogue: row-sum reduce, normalize, residual, store ----
    #pragma unroll
    for (int tm = 0; tm < 2; tm++) {
        float s0 = srow[tm][0];
        s0 += __shfl_xor_sync(0xffffffffu, s0, 1);
        s0 += __shfl_xor_sync(0xffffffffu, s0, 2);
        float s1 = srow[tm][1];
        s1 += __shfl_xor_sync(0xffffffffu, s1, 1);
        s1 += __shfl_xor_sync(0xffffffffu, s1, 2);
        float inv0 = 1.f / s0, inv1 = 1.f / s1;
        int e_lo = wid * 32 + tm * 16 + g4;
        #pragma unroll
        for (int np = 0; np < 2; np++) {
            int p = np * 8 + l4 * 2;
            size_t lo = (size_t)b * FEAT + e_lo * 16 + p;
            size_t hi = lo + 8 * 16;
            float2 x0 = *(const float2*)(x + lo);
            float2 x1 = *(const float2*)(x + hi);
            *(float2*)(out + lo) = make_float2(av[tm][np][0] * inv0 + x0.x,
                                               av[tm][np][1] * inv0 + x0.y);
            *(float2*)(out + hi) = make_float2(av[tm][np][2] * inv1 + x1.x,
                                               av[tm][np][3] * inv1 + x1.y);
        }
    }
}

// ---------------- launcher ----------------
extern "C" void kernel_launch(void* const* d_in, const int* in_sizes, int n_in,
                              void* d_out, int out_size) {
    const float* x     = (const float*)d_in[0];
    const float* WQ_w  = (const float*)d_in[1];
    const float* WQ_b  = (const float*)d_in[2];
    const float* WK_w  = (const float*)d_in[3];
    const float* WK_b  = (const float*)d_in[4];
    const float* WV_w  = (const float*)d_in[5];
    const float* WV_b  = (const float*)d_in[6];
    const float* gamma = (const float*)d_in[7];
    const float* beta  = (const float*)d_in[8];
    float* out = (float*)d_out;

    cudaFuncSetAttribute(gemm_mma, cudaFuncAttributeMaxDynamicSharedMemorySize,
                         SMEM_GEMM);
    cudaFuncSetAttribute(attn_tc, cudaFuncAttributeMaxDynamicSharedMemorySize,
                         SMEM_ATTN);

    bn_pass1<<<dim3(FEAT / 256, RCHUNKS), 256>>>(x);
    bn_pass2<<<FEAT / 256, 256>>>(gamma, beta);
    gemm_mma<<<dim3(3, 512), 256, SMEM_GEMM>>>(x, WQ_w, WK_w, WV_w,
                                               WQ_b, WK_b, WV_b);
    attn_tc<<<BATCH, 256, SMEM_ATTN>>>(x, out);
}

// round 7
// speedup vs baseline: 2.0550x; 1.0776x over previous
#include <cuda_runtime.h>
#include <stdint.h>

// Problem constants
#define BATCH 4096
#define FEAT  4096
#define NP    16
#define DDIM  256
#define MROWS (BATCH * NP)   // 65536
#define EPS   1e-5f
#define INV_SCALE 0.0625f    // 1/sqrt(256)
#define QPRE   0.09017131f   // INV_SCALE * log2(e)

// ---------------- device scratch ----------------
#define RCHUNKS 32
__device__ float g_psum[RCHUNKS * FEAT];
__device__ float g_psumsq[RCHUNKS * FEAT];
__device__ float g_scale[FEAT];
__device__ float g_shift[FEAT];
__device__ float g_q[(size_t)MROWS * DDIM];
__device__ float g_k[(size_t)MROWS * DDIM];
__device__ float g_v[(size_t)MROWS * DDIM];

// bf16 2-way split of a fp32 pair: (hi_pair, lo_pair); lower half = y0.
__device__ __forceinline__ uint2 bfsplit2(float y0, float y1) {
    uint32_t hi;
    asm("cvt.rn.bf16x2.f32 %0, %1, %2;" : "=r"(hi) : "f"(y1), "f"(y0));
    float h0 = __uint_as_float(hi << 16);
    float h1 = __uint_as_float(hi & 0xffff0000u);
    uint32_t lo;
    asm("cvt.rn.bf16x2.f32 %0, %1, %2;" : "=r"(lo) : "f"(y1 - h1), "f"(y0 - h0));
    return make_uint2(hi, lo);
}
__device__ __forceinline__ uint32_t bfpack(float y0, float y1) {
    uint32_t h;
    asm("cvt.rn.bf16x2.f32 %0, %1, %2;" : "=r"(h) : "f"(y1), "f"(y0));
    return h;
}
__device__ __forceinline__ float ex2(float x) {
    float r;
    asm("ex2.approx.f32 %0, %1;" : "=f"(r) : "f"(x));
    return r;
}

#define MMA_BF16(c, a0, a1, a2, a3, b0, b1)                                \
    asm volatile(                                                          \
        "mma.sync.aligned.m16n8k16.row.col.f32.bf16.bf16.f32 "             \
        "{%0,%1,%2,%3}, {%4,%5,%6,%7}, {%8,%9}, {%0,%1,%2,%3};"            \
        : "+f"((c)[0]), "+f"((c)[1]), "+f"((c)[2]), "+f"((c)[3])           \
        : "r"(a0), "r"(a1), "r"(a2), "r"(a3), "r"(b0), "r"(b1))

// ---------------- BN pass 1 ----------------
__global__ void bn_pass1(const float* __restrict__ x) {
    int col = blockIdx.x * 256 + threadIdx.x;
    int r0  = blockIdx.y * (BATCH / RCHUNKS);
    float s = 0.f, ss = 0.f;
    #pragma unroll 4
    for (int r = 0; r < BATCH / RCHUNKS; r++) {
        float v = x[(size_t)(r0 + r) * FEAT + col];
        s += v; ss += v * v;
    }
    g_psum[blockIdx.y * FEAT + col]   = s;
    g_psumsq[blockIdx.y * FEAT + col] = ss;
}

// ---------------- BN pass 2 ----------------
__global__ void bn_pass2(const float* __restrict__ gamma,
                         const float* __restrict__ beta) {
    int col = blockIdx.x * blockDim.x + threadIdx.x;
    float s = 0.f, ss = 0.f;
    #pragma unroll
    for (int c = 0; c < RCHUNKS; c++) {
        s  += g_psum[c * FEAT + col];
        ss += g_psumsq[c * FEAT + col];
    }
    float mean = s * (1.f / BATCH);
    float var  = ss * (1.f / BATCH) - mean * mean;
    float rstd = rsqrtf(var + EPS);
    float a = rstd * gamma[col];
    g_scale[col] = a;
    g_shift[col] = beta[col] - mean * a;
}

// ---------------- bf16-split QKV GEMM, term-major mma order ---------------
#define PA   12
#define A_U2 (128 * PA)
#define B_U2 (256 * PA)
#define SMEM_GEMM ((2 * A_U2 + 2 * B_U2) * 8)   // 73728 bytes

__global__ void __launch_bounds__(256, 1) gemm_mma(
    const float* __restrict__ x,
    const float* __restrict__ wq, const float* __restrict__ wk,
    const float* __restrict__ wv,
    const float* __restrict__ bq, const float* __restrict__ bk_,
    const float* __restrict__ bv)
{
    extern __shared__ uint2 sm[];
    const int tid = threadIdx.x;
    const int w   = blockIdx.x;
    const int m0  = blockIdx.y * 128;

    const float* W    = (w == 0) ? wq : (w == 1) ? wk : wv;
    const float* bias = (w == 0) ? bq : (w == 1) ? bk_ : bv;
    float*       out  = (w == 0) ? g_q : (w == 1) ? g_k : g_v;

    const int lane = tid & 31, wid = tid >> 5;
    const int wm = wid >> 2;
    const int wn = wid & 3;
    const int g4 = lane >> 2, l4 = lane & 3;

    const int arow = tid >> 1;
    const int akc  = (tid & 1) * 8;
    const int apb  = (tid & 1) * 4;
    const int brow = tid;
    const float* asrc = x + (size_t)(m0 + arow) * DDIM;
    const float* bsrc = W + (size_t)brow * DDIM;
    const int fcb = (arow & 15) * 256;

    float acc[4][8][4];
    #pragma unroll
    for (int tm = 0; tm < 4; tm++)
        #pragma unroll
        for (int nt = 0; nt < 8; nt++)
            #pragma unroll
            for (int i = 0; i < 4; i++) acc[tm][nt][i] = 0.f;

    float4 pa0, pa1, pb0, pb1, pb2, pb3;

    auto LDG = [&](int c) {
        int kabs = c * 16;
        pa0 = *(const float4*)(asrc + kabs + akc);
        pa1 = *(const float4*)(asrc + kabs + akc + 4);
        pb0 = *(const float4*)(bsrc + kabs);
        pb1 = *(const float4*)(bsrc + kabs + 4);
        pb2 = *(const float4*)(bsrc + kabs + 8);
        pb3 = *(const float4*)(bsrc + kabs + 12);
    };

    auto CVT_STS = [&](int c, int st) {
        int kabs = c * 16;
        const float4 sc0 = *(const float4*)(g_scale + fcb + kabs + akc);
        const float4 sc1 = *(const float4*)(g_scale + fcb + kabs + akc + 4);
        const float4 sh0 = *(const float4*)(g_shift + fcb + kabs + akc);
        const float4 sh1 = *(const float4*)(g_shift + fcb + kabs + akc + 4);
        float y0 = fmaf(pa0.x, sc0.x, sh0.x);
        float y1 = fmaf(pa0.y, sc0.y, sh0.y);
        float y2 = fmaf(pa0.z, sc0.z, sh0.z);
        float y3 = fmaf(pa0.w, sc0.w, sh0.w);
        float y4 = fmaf(pa1.x, sc1.x, sh1.x);
        float y5 = fmaf(pa1.y, sc1.y, sh1.y);
        float y6 = fmaf(pa1.z, sc1.z, sh1.z);
        float y7 = fmaf(pa1.w, sc1.w, sh1.w);
        uint2* adst = sm + (size_t)st * A_U2 + arow * PA + apb;
        adst[0] = bfsplit2(y0, y1);
        adst[1] = bfsplit2(y2, y3);
        adst[2] = bfsplit2(y4, y5);
        adst[3] = bfsplit2(y6, y7);
        uint2* bdst = sm + 2 * A_U2 + (size_t)st * B_U2 + brow * PA;
        bdst[0] = bfsplit2(pb0.x, pb0.y);
        bdst[1] = bfsplit2(pb0.z, pb0.w);
        bdst[2] = bfsplit2(pb1.x, pb1.y);
        bdst[3] = bfsplit2(pb1.z, pb1.w);
        bdst[4] = bfsplit2(pb2.x, pb2.y);
        bdst[5] = bfsplit2(pb2.z, pb2.w);
        bdst[6] = bfsplit2(pb3.x, pb3.y);
        bdst[7] = bfsplit2(pb3.z, pb3.w);
    };

    auto MMA_CHUNK = [&](int st) {
        const uint2* A0 = sm + (size_t)st * A_U2 + (wm * 64) * PA;
        const uint2* B0 = sm + 2 * A_U2 + (size_t)st * B_U2 + (wn * 64) * PA;
        uint2 af[4][4];
        #pragma unroll
        for (int tm = 0; tm < 4; tm++) {
            int r = tm * 16 + g4;
            af[tm][0] = A0[r * PA + l4];
            af[tm][1] = A0[(r + 8) * PA + l4];
            af[tm][2] = A0[r * PA + l4 + 4];
            af[tm][3] = A0[(r + 8) * PA + l4 + 4];
        }
        #pragma unroll
        for (int ng = 0; ng < 2; ng++) {
            uint2 fb0[4], fb1[4];
            #pragma unroll
            for (int j = 0; j < 4; j++) {
                int nt = ng * 4 + j;
                fb0[j] = B0[(nt * 8 + g4) * PA + l4];
                fb1[j] = B0[(nt * 8 + g4) * PA + l4 + 4];
            }
            // term-major: 16 independent accs per term sweep
            #pragma unroll
            for (int j = 0; j < 4; j++)
                #pragma unroll
                for (int tm = 0; tm < 4; tm++)
                    MMA_BF16(acc[tm][ng * 4 + j], af[tm][0].x, af[tm][1].x,
                             af[tm][2].x, af[tm][3].x, fb0[j].x, fb1[j].x);
            #pragma unroll
            for (int j = 0; j < 4; j++)
                #pragma unroll
                for (int tm = 0; tm < 4; tm++)
                    MMA_BF16(acc[tm][ng * 4 + j], af[tm][0].x, af[tm][1].x,
                             af[tm][2].x, af[tm][3].x, fb0[j].y, fb1[j].y);
            #pragma unroll
            for (int j = 0; j < 4; j++)
                #pragma unroll
                for (int tm = 0; tm < 4; tm++)
                    MMA_BF16(acc[tm][ng * 4 + j], af[tm][0].y, af[tm][1].y,
                             af[tm][2].y, af[tm][3].y, fb0[j].x, fb1[j].x);
        }
    };

    LDG(0);
    CVT_STS(0, 0);
    __syncthreads();
    #pragma unroll 1
    for (int c = 0; c < 16; c++) {
        if (c < 15) LDG(c + 1);
        MMA_CHUNK(c & 1);
        if (c < 15) {
            CVT_STS(c + 1, (c + 1) & 1);
            __syncthreads();
        }
    }

    const int rbase = m0 + wm * 64;
    const int cbase = wn * 64;
    #pragma unroll
    for (int tm = 0; tm < 4; tm++) {
        int row = rbase + tm * 16 + g4;
        #pragma unroll
        for (int nt = 0; nt < 8; nt++) {
            int col = cbase + nt * 8 + l4 * 2;
            float2 bb = *(const float2*)(bias + col);
            *(float2*)(out + (size_t)row * DDIM + col) =
                make_float2(acc[tm][nt][0] + bb.x, acc[tm][nt][1] + bb.y);
            *(float2*)(out + (size_t)(row + 8) * DDIM + col) =
                make_float2(acc[tm][nt][2] + bb.x, acc[tm][nt][3] + bb.y);
        }
    }
}

// ---------------- tensor-core attention, term-major + 1-term AV ------------
#define APITCH 12
#define VPITCH 132
#define SMEM_ATTN (2 * 256 * APITCH * 8 + 16 * VPITCH * 4)   // 57600 B

__global__ void __launch_bounds__(256, 1) attn_tc(const float* __restrict__ x,
                                                  float* __restrict__ out)
{
    extern __shared__ uint2 smq[];
    uint2* Qt = smq;                          // [e][p-pair] (hi,lo), pre-scaled
    uint2* Kt = smq + 256 * APITCH;           // [f][p-pair] (hi,lo)
    uint32_t* Vh = (uint32_t*)(smq + 2 * 256 * APITCH);  // [p][f-pair] hi

    const int b = blockIdx.x;
    const int tid = threadIdx.x;
    const int lane = tid & 31, wid = tid >> 5;
    const int g4 = lane >> 2, l4 = lane & 3;

    // ---- load + transpose + split Q (pre-scaled by QPRE) and K ----
    {
        const int j  = tid & 7;
        const int e0 = (tid >> 3) * 8;
        const float* q0p = g_q + (size_t)b * 4096 + (2 * j) * 256 + e0;
        const float* k0p = g_k + (size_t)b * 4096 + (2 * j) * 256 + e0;
        float4 qa = *(const float4*)q0p;
        float4 qb = *(const float4*)(q0p + 4);
        float4 qc = *(const float4*)(q0p + 256);
        float4 qd = *(const float4*)(q0p + 260);
        float q0[8] = {qa.x, qa.y, qa.z, qa.w, qb.x, qb.y, qb.z, qb.w};
        float q1[8] = {qc.x, qc.y, qc.z, qc.w, qd.x, qd.y, qd.z, qd.w};
        #pragma unroll
        for (int i = 0; i < 8; i++)
            Qt[(e0 + i) * APITCH + j] = bfsplit2(q0[i] * QPRE, q1[i] * QPRE);
        float4 ka = *(const float4*)k0p;
        float4 kb = *(const float4*)(k0p + 4);
        float4 kc = *(const float4*)(k0p + 256);
        float4 kd = *(const float4*)(k0p + 260);
        float k0[8] = {ka.x, ka.y, ka.z, ka.w, kb.x, kb.y, kb.z, kb.w};
        float k1[8] = {kc.x, kc.y, kc.z, kc.w, kd.x, kd.y, kd.z, kd.w};
        #pragma unroll
        for (int i = 0; i < 8; i++)
            Kt[(e0 + i) * APITCH + j] = bfsplit2(k0[i], k1[i]);
    }
    // ---- V: [p][f-pair] hi only ----
    {
        const int p  = tid >> 4;
        const int fq = (tid & 15) * 16;
        const float* vp = g_v + (size_t)b * 4096 + p * 256 + fq;
        #pragma unroll
        for (int h = 0; h < 2; h++) {
            float4 v0 = *(const float4*)(vp + h * 8);
            float4 v1 = *(const float4*)(vp + h * 8 + 4);
            uint32_t* d = Vh + p * VPITCH + (fq >> 1) + h * 4;
            d[0] = bfpack(v0.x, v0.y);
            d[1] = bfpack(v0.z, v0.w);
            d[2] = bfpack(v1.x, v1.y);
            d[3] = bfpack(v1.z, v1.w);
        }
    }
    __syncthreads();

    // ---- persistent Q fragments ----
    uint2 af[2][4];
    #pragma unroll
    for (int tm = 0; tm < 2; tm++) {
        int eb = wid * 32 + tm * 16;
        af[tm][0] = Qt[(eb + g4) * APITCH + l4];
        af[tm][1] = Qt[(eb + g4 + 8) * APITCH + l4];
        af[tm][2] = Qt[(eb + g4) * APITCH + l4 + 4];
        af[tm][3] = Qt[(eb + g4 + 8) * APITCH + l4 + 4];
    }

    float av[2][2][4];
    #pragma unroll
    for (int tm = 0; tm < 2; tm++)
        #pragma unroll
        for (int np = 0; np < 2; np++)
            #pragma unroll
            for (int i = 0; i < 4; i++) av[tm][np][i] = 0.f;
    float srow[2][2] = {{0.f, 0.f}, {0.f, 0.f}};

    #pragma unroll
    for (int fc = 0; fc < 256; fc += 64) {
        float E[2][8][4];
        // ---- S chunk: term-major in groups of 4 n-tiles ----
        #pragma unroll
        for (int ng = 0; ng < 2; ng++) {
            uint2 kb0[4], kb1[4];
            #pragma unroll
            for (int j = 0; j < 4; j++) {
                int f = fc + (ng * 4 + j) * 8 + g4;
                kb0[j] = Kt[f * APITCH + l4];
                kb1[j] = Kt[f * APITCH + l4 + 4];
            }
            #pragma unroll
            for (int j = 0; j < 4; j++)
                #pragma unroll
                for (int tm = 0; tm < 2; tm++) {
                    float* c = E[tm][ng * 4 + j];
                    c[0] = c[1] = c[2] = c[3] = 0.f;
                }
            #pragma unroll
            for (int j = 0; j < 4; j++)
                #pragma unroll
                for (int tm = 0; tm < 2; tm++)
                    MMA_BF16(E[tm][ng * 4 + j], af[tm][0].x, af[tm][1].x,
                             af[tm][2].x, af[tm][3].x, kb0[j].x, kb1[j].x);
            #pragma unroll
            for (int j = 0; j < 4; j++)
                #pragma unroll
                for (int tm = 0; tm < 2; tm++)
                    MMA_BF16(E[tm][ng * 4 + j], af[tm][0].x, af[tm][1].x,
                             af[tm][2].x, af[tm][3].x, kb0[j].y, kb1[j].y);
            #pragma unroll
            for (int j = 0; j < 4; j++)
                #pragma unroll
                for (int tm = 0; tm < 2; tm++)
                    MMA_BF16(E[tm][ng * 4 + j], af[tm][0].y, af[tm][1].y,
                             af[tm][2].y, af[tm][3].y, kb0[j].x, kb1[j].x);
        }
        // ---- exp2 + row sums (Q pre-scaled; arg already in log2 units) ----
        #pragma unroll
        for (int tm = 0; tm < 2; tm++)
            #pragma unroll
            for (int nt = 0; nt < 8; nt++) {
                float* c = E[tm][nt];
                c[0] = ex2(c[0]);
                c[1] = ex2(c[1]);
                c[2] = ex2(c[2]);
                c[3] = ex2(c[3]);
                srow[tm][0] += c[0] + c[1];
                srow[tm][1] += c[2] + c[3];
            }
        // ---- AV: P (bf16 hi) x V_hi, single term ----
        #pragma unroll
        for (int s = 0; s < 4; s++) {
            uint32_t vb0[2], vb1[2];
            #pragma unroll
            for (int np = 0; np < 2; np++) {
                const uint32_t* vr = Vh + (np * 8 + g4) * VPITCH + (fc >> 1) + s * 8;
                vb0[np] = vr[l4];
                vb1[np] = vr[l4 + 4];
            }
            #pragma unroll
            for (int tm = 0; tm < 2; tm++) {
                uint32_t a0 = bfpack(E[tm][2 * s][0], E[tm][2 * s][1]);
                uint32_t a1 = bfpack(E[tm][2 * s][2], E[tm][2 * s][3]);
                uint32_t a2 = bfpack(E[tm][2 * s + 1][0], E[tm][2 * s + 1][1]);
                uint32_t a3 = bfpack(E[tm][2 * s + 1][2], E[tm][2 * s + 1][3]);
                #pragma unroll
                for (int np = 0; np < 2; np++)
                    MMA_BF16(av[tm][np], a0, a1, a2, a3, vb0[np], vb1[np]);
            }
        }
    }

    // ---- epilogue ----
    #pragma unroll
    for (int tm = 0; tm < 2; tm++) {
        float s0 = srow[tm][0];
        s0 += __shfl_xor_sync(0xffffffffu, s0, 1);
        s0 += __shfl_xor_sync(0xffffffffu, s0, 2);
        float s1 = srow[tm][1];
        s1 += __shfl_xor_sync(0xffffffffu, s1, 1);
        s1 += __shfl_xor_sync(0xffffffffu, s1, 2);
        float inv0 = 1.f / s0, inv1 = 1.f / s1;
        int e_lo = wid * 32 + tm * 16 + g4;
        #pragma unroll
        for (int np = 0; np < 2; np++) {
            int p = np * 8 + l4 * 2;
            size_t lo = (size_t)b * FEAT + e_lo * 16 + p;
            size_t hi = lo + 8 * 16;
            float2 x0 = *(const float2*)(x + lo);
            float2 x1 = *(const float2*)(x + hi);
            *(float2*)(out + lo) = make_float2(av[tm][np][0] * inv0 + x0.x,
                                               av[tm][np][1] * inv0 + x0.y);
            *(float2*)(out + hi) = make_float2(av[tm][np][2] * inv1 + x1.x,
                                               av[tm][np][3] * inv1 + x1.y);
        }
    }
}

// ---------------- launcher ----------------
extern "C" void kernel_launch(void* const* d_in, const int* in_sizes, int n_in,
                              void* d_out, int out_size) {
    const float* x     = (const float*)d_in[0];
    const float* WQ_w  = (const float*)d_in[1];
    const float* WQ_b  = (const float*)d_in[2];
    const float* WK_w  = (const float*)d_in[3];
    const float* WK_b  = (const float*)d_in[4];
    const float* WV_w  = (const float*)d_in[5];
    const float* WV_b  = (const float*)d_in[6];
    const float* gamma = (const float*)d_in[7];
    const float* beta  = (const float*)d_in[8];
    float* out = (float*)d_out;

    cudaFuncSetAttribute(gemm_mma, cudaFuncAttributeMaxDynamicSharedMemorySize,
                         SMEM_GEMM);
    cudaFuncSetAttribute(attn_tc, cudaFuncAttributeMaxDynamicSharedMemorySize,
                         SMEM_ATTN);

    bn_pass1<<<dim3(FEAT / 256, RCHUNKS), 256>>>(x);
    bn_pass2<<<FEAT / 256, 256>>>(gamma, beta);
    gemm_mma<<<dim3(3, 512), 256, SMEM_GEMM>>>(x, WQ_w, WK_w, WV_w,
                                               WQ_b, WK_b, WV_b);
    attn_tc<<<BATCH, 256, SMEM_ATTN>>>(x, out);
}